// round 13
// baseline (speedup 1.0000x reference)
#include <cuda_runtime.h>
#include <math.h>

#define Nn 10
#define Ee 64
#define Hh 128
#define Wd 256
#define Mm 16
#define HW 32768
#define NEHW 20971520
#define SCALE_O 0.005524271728019903f
#define PI_D 3.141592653589793238462643383279502884

// ---------------- static device scratch ----------------
__device__ float  g_bufA[NEHW];            // 83.9 MB
__device__ float  g_bufB[NEHW];            // 83.9 MB
__device__ unsigned g_xtf[NEHW];           // tf32 bits of updim output (conv input)
__device__ float2 g_fw [Nn*Ee*Hh*Mm];      // W-DFT result
__device__ float2 g_cf [Nn*512*Ee];        // fwd coeff   [n][mode][e]
__device__ float2 g_cf2[Nn*512*Ee];        // spectral out [n][mode][o]
__device__ float2 g_wt [8*256*64*64];      // transposed spectral weights (67 MB)
__device__ float4 g_wc [4*64*64];          // collapsed 2x2 phase conv weights
__device__ unsigned g_wcT[4*4*4*1280];     // pre-staged tf32 W: [ph][cc][tap][eo*20+il]
__device__ float  g_twfw[Wd*32];           // fwd W twiddles [w][2k]=cos,[2k+1]=-sin
__device__ float2 g_twh [Hh*32];           // H twiddles [h][r]
__device__ float  g_tiw [32*Wd];           // inverse-W table [j][w] (scale folded)
__device__ float2 g_pstat[Nn*Ee*512];      // per-(ph,strip,wq) partial (sum, sumsq)
__device__ float2 g_stats[Nn*Ee];          // (mean, inv_std)

__device__ __forceinline__ float gelu_f(float x) {
    return 0.5f * x * (1.0f + erff(x * 0.70710678118654752f));
}

__device__ __forceinline__ unsigned f2tf32(float x) {
    unsigned r;
    asm("cvt.rna.tf32.f32 %0, %1;" : "=r"(r) : "f"(x));
    return r;
}

__device__ __forceinline__ void mma_tf32(
    float& c0, float& c1, float& c2, float& c3,
    unsigned a0, unsigned a1, unsigned a2, unsigned a3,
    unsigned b0, unsigned b1)
{
    asm volatile(
        "mma.sync.aligned.m16n8k8.row.col.f32.tf32.tf32.f32 "
        "{%0,%1,%2,%3}, {%4,%5,%6,%7}, {%8,%9}, {%0,%1,%2,%3};"
        : "+f"(c0), "+f"(c1), "+f"(c2), "+f"(c3)
        : "r"(a0), "r"(a1), "r"(a2), "r"(a3), "r"(b0), "r"(b1));
}

// ---------------- prep kernels ----------------
__global__ void k_prep_tw() {
    int t = blockIdx.x * blockDim.x + threadIdx.x;
    if (t < Wd * Mm) {
        int w = t >> 4, k = t & 15;
        double ang = 2.0 * PI_D * (double)(k * w) / (double)Wd;
        double s, c; sincos(ang, &s, &c);
        g_twfw[w * 32 + 2 * k]     = (float)c;
        g_twfw[w * 32 + 2 * k + 1] = (float)(-s);
        float fk = (k == 0) ? 1.0f : 2.0f;
        g_tiw[(2 * k) * Wd + w]     = fk * (float)c * SCALE_O;
        g_tiw[(2 * k + 1) * Wd + w] = (k == 0) ? 0.0f : (-2.0f * (float)s * SCALE_O);
    } else if (t < 8192) {
        int t2 = t - 4096;
        int h = t2 >> 5, r = t2 & 31;
        int rf = (r < 16) ? r : r + 96;
        double ang = 2.0 * PI_D * (double)(rf * h) / (double)Hh;
        double s, c; sincos(ang, &s, &c);
        g_twh[h * 32 + r] = make_float2((float)c, (float)s);
    }
}

__device__ __forceinline__ bool in_set(int a, int s, int k) {
    return a == 0 ? (s == 0 ? (k == 0) : (k >= 1))
                  : (s == 0 ? (k <= 1) : (k == 2));
}

__global__ void k_prep_wc(const float* __restrict__ w3) {
    int t = blockIdx.x * blockDim.x + threadIdx.x;
    if (t >= 16384) return;
    int ph = t >> 12;
    int o  = (t >> 6) & 63;
    int i  = t & 63;
    int a = ph >> 1, b = ph & 1;
    const float* wk = w3 + (o * 64 + i) * 9;
    float v[4];
    #pragma unroll
    for (int s = 0; s < 2; s++)
        #pragma unroll
        for (int tt = 0; tt < 2; tt++) {
            float acc = 0.f;
            for (int ky = 0; ky < 3; ky++)
                if (in_set(a, s, ky))
                    for (int kx = 0; kx < 3; kx++)
                        if (in_set(b, tt, kx)) acc += wk[ky * 3 + kx];
            v[s * 2 + tt] = acc;
        }
    g_wc[t] = make_float4(v[0], v[1], v[2], v[3]);
}

// pre-stage W into the exact per-chunk wsm image (tf32 bits, stride-20 rows)
__global__ void k_prep_wcT() {
    int t = blockIdx.x * blockDim.x + threadIdx.x;   // 65536
    if (t >= 65536) return;
    int il  = t & 15;
    int eo  = (t >> 4) & 63;
    int tap = (t >> 10) & 3;
    int cc  = (t >> 12) & 3;
    int ph  = t >> 14;
    float val = ((const float*)g_wc)[(size_t)(ph * 4096 + eo * 64 + cc * 16 + il) * 4 + tap];
    g_wcT[(size_t)(((ph * 4 + cc) * 4 + tap)) * 1280 + eo * 20 + il] = f2tf32(val);
}

__global__ void k_prep_wt(const float* __restrict__ wr, const float* __restrict__ wi) {
    int t = blockIdx.x * blockDim.x + threadIdx.x;   // 8388608 total
    int m  = t & 255;
    int o  = (t >> 8) & 63;
    int i  = (t >> 14) & 63;
    int lq = t >> 20;
    int src = (((lq * 64 + i) * 64 + o) << 8) + m;
    g_wt[((size_t)(lq * 256 + m) * 64 + i) * 64 + o] = make_float2(wr[src], wi[src]);
}

// ---------------- pipeline ----------------
// updim writes ONLY tf32 bits (g_xtf) — its fp32 result was only read by conv.
__global__ void k_updim(const float* __restrict__ in, const float* __restrict__ uw,
                        const float* __restrict__ ub) {
    int idx = blockIdx.x * blockDim.x + threadIdx.x;   // NEHW/4 threads
    if (idx >= NEHW / 4) return;
    int p4 = (idx & 8191) << 2;
    int ne = idx >> 13;
    int e = ne & 63, n = ne >> 6;
    float4 x0 = *(const float4*)&in[(size_t)(n * 2)     * HW + p4];
    float4 x1 = *(const float4*)&in[(size_t)(n * 2 + 1) * HW + p4];
    float w0 = uw[e * 2], w1 = uw[e * 2 + 1], b = ub[e];
    uint4 t;
    t.x = f2tf32(fmaf(w0, x0.x, fmaf(w1, x1.x, b)));
    t.y = f2tf32(fmaf(w0, x0.y, fmaf(w1, x1.y, b)));
    t.z = f2tf32(fmaf(w0, x0.z, fmaf(w1, x1.z, b)));
    t.w = f2tf32(fmaf(w0, x0.w, fmaf(w1, x1.w, b)));
    *(uint4*)&g_xtf[(size_t)ne * HW + p4] = t;
}

// 4-phase collapsed conv via tf32 mma.sync (m16n8k8), v2.1:
// x pre-converted (g_xtf), W pre-staged (g_wcT -> uint4 copy), interior fast path.
__global__ __launch_bounds__(256, 2) void k_conv_mma() {
    __shared__ __align__(16) unsigned wsm[4 * 1280];  // [tap][eo*20 + il]
    __shared__ __align__(16) unsigned xsm[6336];      // 8 pairs * 396 * 2 words
    __shared__ float2 sred[64][2];
    int tid = threadIdx.x;
    int ph = blockIdx.x >> 2, wq = blockIdx.x & 3;
    int strip = blockIdx.y, n = blockIdx.z;
    int h0 = strip * 4, w0 = wq * 64;
    int a_ = ph >> 1, b_ = ph & 1;
    int lane = tid & 31, warp = tid >> 5;
    int mt = warp & 3, ng = warp >> 2;
    int tig = lane & 3, g = lane >> 2;
    bool interior = (strip >= 1 && strip <= 30);

    float C[2][8][4];
    #pragma unroll
    for (int hh = 0; hh < 2; hh++)
        #pragma unroll
        for (int wt = 0; wt < 8; wt++)
            #pragma unroll
            for (int c = 0; c < 4; c++) C[hh][wt][c] = 0.f;

    int colm = tid & 63;
    int rowi = tid >> 6;
    int hcr = tid >> 1;
    int hside = tid & 1;
    int hch = hcr / 6;
    int hrow = hcr - hch * 6;
    int hcol = hside ? 65 : 0;

    const unsigned* xtb = g_xtf + (size_t)(n * 64) * HW;
    for (int cc = 0; cc < 4; cc++) {
        __syncthreads();
        // ---- stage x chunk main region (cols 1..64) ----
        if (interior) {
            int ch = 0, row = rowi;
            const unsigned* base = xtb + (size_t)(cc * 16) * HW + (h0 - 1) * Wd + w0 + colm;
            #pragma unroll 4
            for (int it = 0; it < 24; it++) {
                unsigned v = base[(size_t)ch * HW + row * Wd];
                int word = ((ch >> 3) * 4 + (ch & 3)) * 792
                         + (row * 66 + colm + 1) * 2 + ((ch >> 2) & 1);
                xsm[word] = v;
                row += 4;
                if (row >= 6) { row -= 6; ch += 1; }
            }
        } else {
            int ch = 0, row = rowi;
            #pragma unroll 4
            for (int it = 0; it < 24; it++) {
                int gh = h0 - 1 + row;
                unsigned v = 0u;
                if (gh >= 0 && gh < Hh)
                    v = xtb[(size_t)(cc * 16 + ch) * HW + gh * Wd + (w0 + colm)];
                int word = ((ch >> 3) * 4 + (ch & 3)) * 792
                         + (row * 66 + colm + 1) * 2 + ((ch >> 2) & 1);
                xsm[word] = v;
                row += 4;
                if (row >= 6) { row -= 6; ch += 1; }
            }
        }
        // ---- halo cols 0 and 65 ----
        if (tid < 192) {
            int gh = h0 - 1 + hrow;
            int gw = w0 - 1 + hcol;
            unsigned v = 0u;
            if (gh >= 0 && gh < Hh && gw >= 0 && gw < Wd)
                v = xtb[(size_t)(cc * 16 + hch) * HW + gh * Wd + gw];
            int word = ((hch >> 3) * 4 + (hch & 3)) * 792
                     + (hrow * 66 + hcol) * 2 + ((hch >> 2) & 1);
            xsm[word] = v;
        }
        // ---- stage W chunk: pure uint4 copy of pre-laid-out image ----
        {
            const uint4* wsrc = (const uint4*)&g_wcT[(size_t)((ph * 4 + cc) * 4) * 1280];
            uint4* wdst = (uint4*)wsm;
            #pragma unroll
            for (int j = 0; j < 5; j++)
                wdst[tid + j * 256] = wsrc[tid + j * 256];
        }
        __syncthreads();
        #pragma unroll
        for (int tap = 0; tap < 4; tap++) {
            int rowadd = a_ + (tap >> 1);
            int coladd = b_ + (tap & 1);
            unsigned Af[2][4];
            #pragma unroll
            for (int ks = 0; ks < 2; ks++) {
                int ab = tap * 1280 + (mt * 16 + g) * 20 + ks * 8 + tig;
                Af[ks][0] = wsm[ab];
                Af[ks][1] = wsm[ab + 160];
                Af[ks][2] = wsm[ab + 4];
                Af[ks][3] = wsm[ab + 164];
            }
            #pragma unroll
            for (int ks = 0; ks < 2; ks++) {
                int wbase = (ks * 4 + tig) * 792
                          + (2 * ng + rowadd) * 132 + (g + coladd) * 2;
                #pragma unroll
                for (int hh = 0; hh < 2; hh++) {
                    #pragma unroll
                    for (int wt = 0; wt < 8; wt++) {
                        uint2 bv = *(const uint2*)&xsm[wbase + hh * 132 + wt * 16];
                        mma_tf32(C[hh][wt][0], C[hh][wt][1], C[hh][wt][2], C[hh][wt][3],
                                 Af[ks][0], Af[ks][1], Af[ks][2], Af[ks][3],
                                 bv.x, bv.y);
                    }
                }
            }
        }
    }

    // phase (0,0) is the carried value (resize takes even pixels)
    if (ph == 0) {
        #pragma unroll
        for (int hh = 0; hh < 2; hh++) {
            int h = h0 + 2 * ng + hh;
            #pragma unroll
            for (int wt = 0; wt < 8; wt++) {
                int w = w0 + wt * 8 + 2 * tig;
                int eo = mt * 16 + g;
                *(float2*)&g_bufB[((size_t)(n * 64 + eo) * Hh + h) * Wd + w] =
                    make_float2(C[hh][wt][0], C[hh][wt][1]);
                *(float2*)&g_bufB[((size_t)(n * 64 + eo + 8) * Hh + h) * Wd + w] =
                    make_float2(C[hh][wt][2], C[hh][wt][3]);
            }
        }
    }
    // deterministic partial stats
    float s0 = 0.f, q0 = 0.f, s1 = 0.f, q1 = 0.f;
    #pragma unroll
    for (int hh = 0; hh < 2; hh++)
        #pragma unroll
        for (int wt = 0; wt < 8; wt++) {
            float v0 = C[hh][wt][0], v1 = C[hh][wt][1];
            float v2 = C[hh][wt][2], v3 = C[hh][wt][3];
            s0 += v0 + v1; q0 += v0 * v0 + v1 * v1;
            s1 += v2 + v3; q1 += v2 * v2 + v3 * v3;
        }
    #pragma unroll
    for (int off = 1; off <= 2; off <<= 1) {
        s0 += __shfl_xor_sync(0xffffffffu, s0, off);
        q0 += __shfl_xor_sync(0xffffffffu, q0, off);
        s1 += __shfl_xor_sync(0xffffffffu, s1, off);
        q1 += __shfl_xor_sync(0xffffffffu, q1, off);
    }
    if ((lane & 3) == 0) {
        sred[mt * 16 + g][ng]     = make_float2(s0, q0);
        sred[mt * 16 + g + 8][ng] = make_float2(s1, q1);
    }
    __syncthreads();
    if (tid < 64) {
        float2 p0 = sred[tid][0], p1 = sred[tid][1];
        g_pstat[(size_t)(n * 64 + tid) * 512 + ph * 128 + strip * 4 + wq] =
            make_float2(p0.x + p1.x, p0.y + p1.y);
    }
}

__global__ __launch_bounds__(256) void k_stats() {
    __shared__ float2 red[8];
    int b = blockIdx.x;
    int t = threadIdx.x, lane = t & 31, wid = t >> 5;
    float2 v0 = g_pstat[(size_t)b * 512 + t];
    float2 v1 = g_pstat[(size_t)b * 512 + 256 + t];
    float s = v0.x + v1.x, q = v0.y + v1.y;
    #pragma unroll
    for (int off = 16; off > 0; off >>= 1) {
        s += __shfl_down_sync(0xffffffffu, s, off);
        q += __shfl_down_sync(0xffffffffu, q, off);
    }
    if (lane == 0) red[wid] = make_float2(s, q);
    __syncthreads();
    if (t == 0) {
        float S = 0.f, Q = 0.f;
        #pragma unroll
        for (int i = 0; i < 8; i++) { S += red[i].x; Q += red[i].y; }
        float mean = S * (1.0f / 131072.0f);
        float var  = Q * (1.0f / 131072.0f) - mean * mean;
        g_stats[b] = make_float2(mean, rsqrtf(var + 1e-5f));
    }
}

// conv1x1 (scalar FFMA, validated R10); when first!=0 the input is g_bufB
// (raw conv output): apply InstanceNorm+gelu on load, write x to g_bufA.
__global__ __launch_bounds__(256) void k_conv1x1(const float* __restrict__ cw,
                                                 const float* __restrict__ cb,
                                                 int first) {
    __shared__ float sw[4096];
    __shared__ float sb[64];
    __shared__ float2 sst[64];
    int tid = threadIdx.x;
    int n = blockIdx.y;
    int p = blockIdx.x * 256 + tid;
    for (int idx = tid; idx < 4096; idx += 256) sw[idx] = cw[idx];
    if (tid < 64) {
        sb[tid] = cb[tid];
        if (first) sst[tid] = g_stats[n * 64 + tid];
    }
    __syncthreads();
    float xv[64];
    const float* xb = (first ? g_bufB : g_bufA) + (size_t)n * 64 * HW + p;
    float* xout = g_bufA + (size_t)n * 64 * HW + p;
    #pragma unroll
    for (int i = 0; i < 64; i++) {
        float v = xb[(size_t)i * HW];
        if (first) {
            float2 st = sst[i];
            v = gelu_f((v - st.x) * st.y);
            xout[(size_t)i * HW] = v;
        }
        xv[i] = v;
    }
    float* ob = g_bufB + (size_t)n * 64 * HW + p;
    for (int o = 0; o < 64; o++) {
        float a = sb[o];
        const float4* w4 = (const float4*)(sw + o * 64);
        #pragma unroll
        for (int i4 = 0; i4 < 16; i4++) {
            float4 w = w4[i4];
            a = fmaf(w.x, xv[4 * i4],     a);
            a = fmaf(w.y, xv[4 * i4 + 1], a);
            a = fmaf(w.z, xv[4 * i4 + 2], a);
            a = fmaf(w.w, xv[4 * i4 + 3], a);
        }
        ob[(size_t)o * HW] = a;
    }
}

// forward W-DFT: Zw[row][k] = sum_w x[row][w] * e^{-2pi i k w / 256}
__global__ __launch_bounds__(256) void k_fwdW() {
    __shared__ float smx[32 * 256];
    int tid = threadIdx.x;
    int row0 = blockIdx.x * 32;
    for (int idx = tid; idx < 8192; idx += 256)
        smx[idx] = g_bufA[(size_t)row0 * 256 + idx];
    __syncthreads();
    int k = tid & 15, rg = tid >> 4;
    int r0 = rg * 2, r1 = r0 + 1;
    float a0r = 0, a0i = 0, a1r = 0, a1i = 0;
    const float2* twp = (const float2*)g_twfw;   // [w*16 + k]
    #pragma unroll 2
    for (int w = 0; w < 256; w += 4) {
        float4 x0 = *(const float4*)&smx[r0 * 256 + w];
        float4 x1 = *(const float4*)&smx[r1 * 256 + w];
        float2 t0 = twp[(w + 0) * 16 + k];
        float2 t1 = twp[(w + 1) * 16 + k];
        float2 t2 = twp[(w + 2) * 16 + k];
        float2 t3 = twp[(w + 3) * 16 + k];
        a0r = fmaf(x0.x, t0.x, a0r); a0i = fmaf(x0.x, t0.y, a0i);
        a0r = fmaf(x0.y, t1.x, a0r); a0i = fmaf(x0.y, t1.y, a0i);
        a0r = fmaf(x0.z, t2.x, a0r); a0i = fmaf(x0.z, t2.y, a0i);
        a0r = fmaf(x0.w, t3.x, a0r); a0i = fmaf(x0.w, t3.y, a0i);
        a1r = fmaf(x1.x, t0.x, a1r); a1i = fmaf(x1.x, t0.y, a1i);
        a1r = fmaf(x1.y, t1.x, a1r); a1i = fmaf(x1.y, t1.y, a1i);
        a1r = fmaf(x1.z, t2.x, a1r); a1i = fmaf(x1.z, t2.y, a1i);
        a1r = fmaf(x1.w, t3.x, a1r); a1i = fmaf(x1.w, t3.y, a1i);
    }
    g_fw[(size_t)(row0 + r0) * 16 + k] = make_float2(a0r, a0i);
    g_fw[(size_t)(row0 + r1) * 16 + k] = make_float2(a1r, a1i);
}

// forward H-DFT (rows 0..15 & 112..127), output pair (r, r+16) shares z loads
__global__ __launch_bounds__(256) void k_fwdH() {
    __shared__ float2 smz[2048];
    int tid = threadIdx.x;
    int b = blockIdx.x;          // n*64 + e
    int n = b >> 6, e = b & 63;
    for (int idx = tid; idx < 2048; idx += 256)
        smz[idx] = g_fw[(size_t)b * 2048 + idx];
    __syncthreads();
    int k = tid & 15, rr = tid >> 4;
    float ar0 = 0, ai0 = 0, ar1 = 0, ai1 = 0;
    #pragma unroll 4
    for (int h = 0; h < 128; h++) {
        float2 z = smz[h * 16 + k];
        float2 tA = g_twh[h * 32 + rr];
        float2 tB = g_twh[h * 32 + rr + 16];
        ar0 += z.x * tA.x + z.y * tA.y;
        ai0 += z.y * tA.x - z.x * tA.y;
        ar1 += z.x * tB.x + z.y * tB.y;
        ai1 += z.y * tB.x - z.x * tB.y;
    }
    g_cf[((size_t)n * 512 + rr * 16 + k) * 64 + e] =
        make_float2(ar0 * SCALE_O, ai0 * SCALE_O);
    g_cf[((size_t)n * 512 + (rr + 16) * 16 + k) * 64 + e] =
        make_float2(ar1 * SCALE_O, ai1 * SCALE_O);
}

// spectral multiply: one block per mode m, all 10 batch images per block
__global__ __launch_bounds__(128) void k_spec(int l) {
    __shared__ float2 sc[10][64];
    int tid = threadIdx.x;
    int m = blockIdx.x;            // 0..511
    for (int idx = tid; idx < 640; idx += 128) {
        int n = idx >> 6, i = idx & 63;
        sc[n][i] = g_cf[((size_t)n * 512 + m) * 64 + i];
    }
    __syncthreads();
    int o = tid & 63, nh = tid >> 6;
    int r = m >> 4, k = m & 15;
    int q = r >> 4;
    int m2 = (r & 15) * 16 + k;
    const float2* wp = g_wt + (size_t)((l * 2 + q) * 256 + m2) * 4096 + o;
    float ar[5] = {0, 0, 0, 0, 0}, ai[5] = {0, 0, 0, 0, 0};
    #pragma unroll 2
    for (int i = 0; i < 64; i++) {
        float2 w = wp[(size_t)i * 64];
        #pragma unroll
        for (int j = 0; j < 5; j++) {
            float2 c = sc[nh * 5 + j][i];
            ar[j] = fmaf(c.x, w.x, fmaf(-c.y, w.y, ar[j]));
            ai[j] = fmaf(c.x, w.y, fmaf(c.y, w.x, ai[j]));
        }
    }
    #pragma unroll
    for (int j = 0; j < 5; j++)
        g_cf2[((size_t)(nh * 5 + j) * 512 + m) * 64 + o] = make_float2(ar[j], ai[j]);
}

// FUSED inverse H + inverse W (C2R) + conv1x1-add + gelu.
__global__ __launch_bounds__(256) void k_invHW_gelu() {
    __shared__ float2 sz[512];
    __shared__ float  zz[32][32];
    int tid = threadIdx.x;
    int hq = blockIdx.x;
    int b  = blockIdx.y;             // n*64 + o
    int n = b >> 6, oo = b & 63;
    for (int m = tid; m < 512; m += 256)
        sz[m] = g_cf2[((size_t)n * 512 + m) * 64 + oo];
    __syncthreads();
    for (int oi = tid; oi < 512; oi += 256) {
        int hp = oi >> 4, k = oi & 15;
        int h = hq * 32 + hp;
        float ar = 0, ai = 0;
        #pragma unroll
        for (int r = 0; r < 32; r++) {
            float2 sp = sz[r * 16 + k];
            float2 t = g_twh[h * 32 + r];
            ar += sp.x * t.x - sp.y * t.y;
            ai += sp.x * t.y + sp.y * t.x;
        }
        zz[hp][2 * k]     = ar;
        zz[hp][2 * k + 1] = ai;
    }
    __syncthreads();
    int tx = tid & 63, ry = tid >> 6;
    int w0 = tx * 4;
    const float4* tp = (const float4*)g_tiw;
    size_t rowbase = (size_t)b * 128 + hq * 32;
    #pragma unroll
    for (int rg = 0; rg < 4; rg++) {
        int hA = rg * 8 + ry * 2, hB = hA + 1;
        float aA0 = 0, aA1 = 0, aA2 = 0, aA3 = 0;
        float aB0 = 0, aB1 = 0, aB2 = 0, aB3 = 0;
        #pragma unroll 4
        for (int j = 0; j < 32; j++) {
            float4 tv = tp[j * 64 + tx];
            float zA = zz[hA][j], zB = zz[hB][j];
            aA0 = fmaf(zA, tv.x, aA0); aA1 = fmaf(zA, tv.y, aA1);
            aA2 = fmaf(zA, tv.z, aA2); aA3 = fmaf(zA, tv.w, aA3);
            aB0 = fmaf(zB, tv.x, aB0); aB1 = fmaf(zB, tv.y, aB1);
            aB2 = fmaf(zB, tv.z, aB2); aB3 = fmaf(zB, tv.w, aB3);
        }
        size_t pA = (rowbase + hA) * Wd + w0;
        size_t pB = (rowbase + hB) * Wd + w0;
        float4 cA = *(const float4*)&g_bufB[pA];
        float4 cB = *(const float4*)&g_bufB[pB];
        float4 oA = make_float4(gelu_f(aA0 + cA.x), gelu_f(aA1 + cA.y),
                                gelu_f(aA2 + cA.z), gelu_f(aA3 + cA.w));
        float4 oB = make_float4(gelu_f(aB0 + cB.x), gelu_f(aB1 + cB.y),
                                gelu_f(aB2 + cB.z), gelu_f(aB3 + cB.w));
        *(float4*)&g_bufA[pA] = oA;
        *(float4*)&g_bufA[pB] = oB;
    }
}

__global__ __launch_bounds__(256) void k_downdim(const float* __restrict__ dw,
                                                 const float* __restrict__ db,
                                                 float* __restrict__ out) {
    __shared__ float sdw[128];
    __shared__ float sdb[2];
    int tid = threadIdx.x;
    if (tid < 128) sdw[tid] = dw[tid];
    if (tid < 2) sdb[tid] = db[tid];
    __syncthreads();
    int t = blockIdx.x * blockDim.x + tid;   // Nn*HW/4 threads
    if (t >= Nn * HW / 4) return;
    int n = t >> 13, p4 = (t & 8191) << 2;
    float4 c0 = make_float4(sdb[0], sdb[0], sdb[0], sdb[0]);
    float4 c1 = make_float4(sdb[1], sdb[1], sdb[1], sdb[1]);
    const float* xb = g_bufA + (size_t)n * 64 * HW + p4;
    #pragma unroll 4
    for (int e = 0; e < 64; e++) {
        float4 v = *(const float4*)&xb[(size_t)e * HW];
        float w0 = sdw[e], w1 = sdw[64 + e];
        c0.x = fmaf(w0, v.x, c0.x); c0.y = fmaf(w0, v.y, c0.y);
        c0.z = fmaf(w0, v.z, c0.z); c0.w = fmaf(w0, v.w, c0.w);
        c1.x = fmaf(w1, v.x, c1.x); c1.y = fmaf(w1, v.y, c1.y);
        c1.z = fmaf(w1, v.z, c1.z); c1.w = fmaf(w1, v.w, c1.w);
    }
    *(float4*)&out[(size_t)(n * 2) * HW + p4]     = c0;
    *(float4*)&out[(size_t)(n * 2 + 1) * HW + p4] = c1;
}

extern "C" void kernel_launch(void* const* d_in, const int* in_sizes, int n_in,
                              void* d_out, int out_size) {
    (void)in_sizes; (void)n_in; (void)out_size;
    const float* sensor    = (const float*)d_in[0];
    const float* updim_w   = (const float*)d_in[1];
    const float* updim_b   = (const float*)d_in[2];
    const float* smooth_w  = (const float*)d_in[3];
    // d_in[4] smooth_b: cancels exactly under InstanceNorm(affine=False)
    const float* fno_wr    = (const float*)d_in[5];
    const float* fno_wi    = (const float*)d_in[6];
    const float* fno_cw    = (const float*)d_in[7];
    const float* fno_cb    = (const float*)d_in[8];
    const float* downdim_w = (const float*)d_in[9];
    const float* downdim_b = (const float*)d_in[10];
    float* out = (float*)d_out;

    // DEPENDENCY ORDER: prep_wc -> prep_wcT -> conv_mma; updim -> conv_mma.
    k_prep_tw<<<32, 256>>>();
    k_prep_wc<<<64, 256>>>(smooth_w);
    k_prep_wcT<<<256, 256>>>();
    k_updim<<<NEHW / 4 / 256, 256>>>(sensor, updim_w, updim_b);
    k_conv_mma<<<dim3(16, 32, 10), 256>>>();
    k_stats<<<640, 256>>>();
    k_prep_wt<<<32768, 256>>>(fno_wr, fno_wi);

    for (int l = 0; l < 4; l++) {
        k_conv1x1<<<dim3(128, 10), 256>>>(fno_cw + l * 4096, fno_cb + l * 64,
                                          l == 0 ? 1 : 0);
        k_fwdW<<<2560, 256>>>();
        k_fwdH<<<640, 256>>>();
        k_spec<<<512, 128>>>(l);
        k_invHW_gelu<<<dim3(4, 640), 256>>>();
    }

    k_downdim<<<(Nn * HW / 4 + 255) / 256, 256>>>(downdim_w, downdim_b, out);
}

// round 14
// speedup vs baseline: 1.4003x; 1.4003x over previous
#include <cuda_runtime.h>
#include <math.h>

#define Nn 10
#define Ee 64
#define Hh 128
#define Wd 256
#define Mm 16
#define HW 32768
#define NEHW 20971520
#define SCALE_O 0.005524271728019903f
#define PI_D 3.141592653589793238462643383279502884

// ---------------- static device scratch ----------------
__device__ float  g_bufA[NEHW];            // 83.9 MB
__device__ float  g_bufB[NEHW];            // 83.9 MB
__device__ float2 g_fw [Nn*Ee*Hh*Mm];      // W-DFT result
__device__ float2 g_cf [Nn*512*Ee];        // fwd coeff   [n][mode][e]
__device__ float2 g_cf2[Nn*512*Ee];        // spectral out [n][mode][o]
__device__ float2 g_wt [8*256*64*64];      // transposed spectral weights (67 MB)
__device__ float4 g_wc [4*64*64];          // collapsed 2x2 phase conv weights
__device__ float  g_twfw[Wd*32];           // fwd W twiddles [w][2k]=cos,[2k+1]=-sin
__device__ float2 g_twh [Hh*32];           // H twiddles [h][r]
__device__ float  g_tiw [32*Wd];           // inverse-W table [j][w] (scale folded)
__device__ float2 g_pstat[Nn*Ee*512];      // per-(ph,strip,wq) partial (sum, sumsq)
__device__ float2 g_stats[Nn*Ee];          // (mean, inv_std)

__device__ __forceinline__ float gelu_f(float x) {
    return 0.5f * x * (1.0f + erff(x * 0.70710678118654752f));
}

__device__ __forceinline__ unsigned f2tf32(float x) {
    unsigned r;
    asm("cvt.rna.tf32.f32 %0, %1;" : "=r"(r) : "f"(x));
    return r;
}

__device__ __forceinline__ void mma_tf32(
    float& c0, float& c1, float& c2, float& c3,
    unsigned a0, unsigned a1, unsigned a2, unsigned a3,
    unsigned b0, unsigned b1)
{
    asm volatile(
        "mma.sync.aligned.m16n8k8.row.col.f32.tf32.tf32.f32 "
        "{%0,%1,%2,%3}, {%4,%5,%6,%7}, {%8,%9}, {%0,%1,%2,%3};"
        : "+f"(c0), "+f"(c1), "+f"(c2), "+f"(c3)
        : "r"(a0), "r"(a1), "r"(a2), "r"(a3), "r"(b0), "r"(b1));
}

// ---------------- prep kernels ----------------
__global__ void k_prep_tw() {
    int t = blockIdx.x * blockDim.x + threadIdx.x;
    if (t < Wd * Mm) {
        int w = t >> 4, k = t & 15;
        double ang = 2.0 * PI_D * (double)(k * w) / (double)Wd;
        double s, c; sincos(ang, &s, &c);
        g_twfw[w * 32 + 2 * k]     = (float)c;
        g_twfw[w * 32 + 2 * k + 1] = (float)(-s);
        float fk = (k == 0) ? 1.0f : 2.0f;
        g_tiw[(2 * k) * Wd + w]     = fk * (float)c * SCALE_O;
        g_tiw[(2 * k + 1) * Wd + w] = (k == 0) ? 0.0f : (-2.0f * (float)s * SCALE_O);
    } else if (t < 8192) {
        int t2 = t - 4096;
        int h = t2 >> 5, r = t2 & 31;
        int rf = (r < 16) ? r : r + 96;
        double ang = 2.0 * PI_D * (double)(rf * h) / (double)Hh;
        double s, c; sincos(ang, &s, &c);
        g_twh[h * 32 + r] = make_float2((float)c, (float)s);
    }
}

__device__ __forceinline__ bool in_set(int a, int s, int k) {
    return a == 0 ? (s == 0 ? (k == 0) : (k >= 1))
                  : (s == 0 ? (k <= 1) : (k == 2));
}

__global__ void k_prep_wc(const float* __restrict__ w3) {
    int t = blockIdx.x * blockDim.x + threadIdx.x;
    if (t >= 16384) return;
    int ph = t >> 12;
    int o  = (t >> 6) & 63;
    int i  = t & 63;
    int a = ph >> 1, b = ph & 1;
    const float* wk = w3 + (o * 64 + i) * 9;
    float v[4];
    #pragma unroll
    for (int s = 0; s < 2; s++)
        #pragma unroll
        for (int tt = 0; tt < 2; tt++) {
            float acc = 0.f;
            for (int ky = 0; ky < 3; ky++)
                if (in_set(a, s, ky))
                    for (int kx = 0; kx < 3; kx++)
                        if (in_set(b, tt, kx)) acc += wk[ky * 3 + kx];
            v[s * 2 + tt] = acc;
        }
    g_wc[t] = make_float4(v[0], v[1], v[2], v[3]);
}

__global__ void k_prep_wt(const float* __restrict__ wr, const float* __restrict__ wi) {
    int t = blockIdx.x * blockDim.x + threadIdx.x;   // 8388608 total
    int m  = t & 255;
    int o  = (t >> 8) & 63;
    int i  = (t >> 14) & 63;
    int lq = t >> 20;
    int src = (((lq * 64 + i) * 64 + o) << 8) + m;
    g_wt[((size_t)(lq * 256 + m) * 64 + i) * 64 + o] = make_float2(wr[src], wi[src]);
}

// ---------------- pipeline ----------------
__global__ void k_updim(const float* __restrict__ in, const float* __restrict__ uw,
                        const float* __restrict__ ub) {
    int idx = blockIdx.x * blockDim.x + threadIdx.x;   // NEHW/4 threads
    if (idx >= NEHW / 4) return;
    int p4 = (idx & 8191) << 2;
    int ne = idx >> 13;
    int e = ne & 63, n = ne >> 6;
    float4 x0 = *(const float4*)&in[(size_t)(n * 2)     * HW + p4];
    float4 x1 = *(const float4*)&in[(size_t)(n * 2 + 1) * HW + p4];
    float w0 = uw[e * 2], w1 = uw[e * 2 + 1], b = ub[e];
    float4 r;
    r.x = fmaf(w0, x0.x, fmaf(w1, x1.x, b));
    r.y = fmaf(w0, x0.y, fmaf(w1, x1.y, b));
    r.z = fmaf(w0, x0.z, fmaf(w1, x1.z, b));
    r.w = fmaf(w0, x0.w, fmaf(w1, x1.w, b));
    *(float4*)&g_bufA[(size_t)ne * HW + p4] = r;
}

// 4-phase collapsed conv via tf32 mma.sync (m16n8k8), v2.
// xsm layout: [ks*4+tp][row 0..5][col 0..65][half 0..1] where the (half) pair
// is channels (tp, tp+4) of the ks-group -> one aligned LDS.64 per B fragment,
// conflict-free (pair stride 792 words; half-warp covers all 32 banks).
// Staging is division-free. A fragments hoisted per tap.
__global__ __launch_bounds__(256, 2) void k_conv_mma() {
    __shared__ unsigned wsm[4 * 1280];            // [tap][eo*20 + i], stride 20
    __shared__ __align__(16) unsigned xsm[6336];  // 8 pairs * 396 * 2 words
    __shared__ float2 sred[64][2];
    int tid = threadIdx.x;
    int ph = blockIdx.x >> 2, wq = blockIdx.x & 3;
    int strip = blockIdx.y, n = blockIdx.z;
    int h0 = strip * 4, w0 = wq * 64;
    int a_ = ph >> 1, b_ = ph & 1;
    int lane = tid & 31, warp = tid >> 5;
    int mt = warp & 3, ng = warp >> 2;     // Mtile (16 eo), h-group (2 rows)
    int tig = lane & 3, g = lane >> 2;

    float C[2][8][4];
    #pragma unroll
    for (int hh = 0; hh < 2; hh++)
        #pragma unroll
        for (int wt = 0; wt < 8; wt++)
            #pragma unroll
            for (int c = 0; c < 4; c++) C[hh][wt][c] = 0.f;

    int colm = tid & 63;
    int rowi = tid >> 6;
    int hcr = tid >> 1;
    int hside = tid & 1;
    int hch = hcr / 6;
    int hrow = hcr - hch * 6;
    int hcol = hside ? 65 : 0;

    const float* xb = g_bufA + (size_t)(n * 64) * HW;
    for (int cc = 0; cc < 4; cc++) {
        __syncthreads();
        {
            int ch = 0, row = rowi;
            #pragma unroll 4
            for (int it = 0; it < 24; it++) {
                int gh = h0 - 1 + row;
                float v = 0.f;
                if (gh >= 0 && gh < Hh)
                    v = xb[(size_t)(cc * 16 + ch) * HW + gh * Wd + (w0 + colm)];
                int word = ((ch >> 3) * 4 + (ch & 3)) * 792
                         + (row * 66 + colm + 1) * 2 + ((ch >> 2) & 1);
                xsm[word] = f2tf32(v);
                row += 4;
                if (row >= 6) { row -= 6; ch += 1; }
            }
        }
        if (tid < 192) {
            int gh = h0 - 1 + hrow;
            int gw = w0 - 1 + hcol;
            float v = 0.f;
            if (gh >= 0 && gh < Hh && gw >= 0 && gw < Wd)
                v = xb[(size_t)(cc * 16 + hch) * HW + gh * Wd + gw];
            int word = ((hch >> 3) * 4 + (hch & 3)) * 792
                     + (hrow * 66 + hcol) * 2 + ((hch >> 2) & 1);
            xsm[word] = f2tf32(v);
        }
        for (int idx = tid; idx < 1024; idx += 256) {
            int eo = idx >> 4, il = idx & 15;
            float4 wv = g_wc[ph * 4096 + eo * 64 + cc * 16 + il];
            int base = eo * 20 + il;
            wsm[base]        = f2tf32(wv.x);
            wsm[1280 + base] = f2tf32(wv.y);
            wsm[2560 + base] = f2tf32(wv.z);
            wsm[3840 + base] = f2tf32(wv.w);
        }
        __syncthreads();
        #pragma unroll
        for (int tap = 0; tap < 4; tap++) {
            int rowadd = a_ + (tap >> 1);
            int coladd = b_ + (tap & 1);
            unsigned Af[2][4];
            #pragma unroll
            for (int ks = 0; ks < 2; ks++) {
                int ab = tap * 1280 + (mt * 16 + g) * 20 + ks * 8 + tig;
                Af[ks][0] = wsm[ab];
                Af[ks][1] = wsm[ab + 160];
                Af[ks][2] = wsm[ab + 4];
                Af[ks][3] = wsm[ab + 164];
            }
            #pragma unroll
            for (int ks = 0; ks < 2; ks++) {
                int wbase = (ks * 4 + tig) * 792
                          + (2 * ng + rowadd) * 132 + (g + coladd) * 2;
                #pragma unroll
                for (int hh = 0; hh < 2; hh++) {
                    #pragma unroll
                    for (int wt = 0; wt < 8; wt++) {
                        uint2 bv = *(const uint2*)&xsm[wbase + hh * 132 + wt * 16];
                        mma_tf32(C[hh][wt][0], C[hh][wt][1], C[hh][wt][2], C[hh][wt][3],
                                 Af[ks][0], Af[ks][1], Af[ks][2], Af[ks][3],
                                 bv.x, bv.y);
                    }
                }
            }
        }
    }

    // phase (0,0) is the carried value (resize takes even pixels)
    if (ph == 0) {
        #pragma unroll
        for (int hh = 0; hh < 2; hh++) {
            int h = h0 + 2 * ng + hh;
            #pragma unroll
            for (int wt = 0; wt < 8; wt++) {
                int w = w0 + wt * 8 + 2 * tig;
                int eo = mt * 16 + g;
                *(float2*)&g_bufB[((size_t)(n * 64 + eo) * Hh + h) * Wd + w] =
                    make_float2(C[hh][wt][0], C[hh][wt][1]);
                *(float2*)&g_bufB[((size_t)(n * 64 + eo + 8) * Hh + h) * Wd + w] =
                    make_float2(C[hh][wt][2], C[hh][wt][3]);
            }
        }
    }
    // deterministic partial stats: c0,c1 belong to eo=mt*16+g; c2,c3 to eo+8
    float s0 = 0.f, q0 = 0.f, s1 = 0.f, q1 = 0.f;
    #pragma unroll
    for (int hh = 0; hh < 2; hh++)
        #pragma unroll
        for (int wt = 0; wt < 8; wt++) {
            float v0 = C[hh][wt][0], v1 = C[hh][wt][1];
            float v2 = C[hh][wt][2], v3 = C[hh][wt][3];
            s0 += v0 + v1; q0 += v0 * v0 + v1 * v1;
            s1 += v2 + v3; q1 += v2 * v2 + v3 * v3;
        }
    #pragma unroll
    for (int off = 1; off <= 2; off <<= 1) {
        s0 += __shfl_xor_sync(0xffffffffu, s0, off);
        q0 += __shfl_xor_sync(0xffffffffu, q0, off);
        s1 += __shfl_xor_sync(0xffffffffu, s1, off);
        q1 += __shfl_xor_sync(0xffffffffu, q1, off);
    }
    if ((lane & 3) == 0) {
        sred[mt * 16 + g][ng]     = make_float2(s0, q0);
        sred[mt * 16 + g + 8][ng] = make_float2(s1, q1);
    }
    __syncthreads();
    if (tid < 64) {
        float2 p0 = sred[tid][0], p1 = sred[tid][1];
        g_pstat[(size_t)(n * 64 + tid) * 512 + ph * 128 + strip * 4 + wq] =
            make_float2(p0.x + p1.x, p0.y + p1.y);
    }
}

__global__ __launch_bounds__(256) void k_stats() {
    __shared__ float2 red[8];
    int b = blockIdx.x;
    int t = threadIdx.x, lane = t & 31, wid = t >> 5;
    float2 v0 = g_pstat[(size_t)b * 512 + t];
    float2 v1 = g_pstat[(size_t)b * 512 + 256 + t];
    float s = v0.x + v1.x, q = v0.y + v1.y;
    #pragma unroll
    for (int off = 16; off > 0; off >>= 1) {
        s += __shfl_down_sync(0xffffffffu, s, off);
        q += __shfl_down_sync(0xffffffffu, q, off);
    }
    if (lane == 0) red[wid] = make_float2(s, q);
    __syncthreads();
    if (t == 0) {
        float S = 0.f, Q = 0.f;
        #pragma unroll
        for (int i = 0; i < 8; i++) { S += red[i].x; Q += red[i].y; }
        float mean = S * (1.0f / 131072.0f);
        float var  = Q * (1.0f / 131072.0f) - mean * mean;
        g_stats[b] = make_float2(mean, rsqrtf(var + 1e-5f));
    }
}

// conv1x1; when first!=0 the input is g_bufB (raw conv output): apply
// InstanceNorm+gelu on load and write the normalized x back to g_bufA.
__global__ __launch_bounds__(256) void k_conv1x1(const float* __restrict__ cw,
                                                 const float* __restrict__ cb,
                                                 int first) {
    __shared__ float sw[4096];
    __shared__ float sb[64];
    __shared__ float2 sst[64];
    int tid = threadIdx.x;
    int n = blockIdx.y;
    int p = blockIdx.x * 256 + tid;
    for (int idx = tid; idx < 4096; idx += 256) sw[idx] = cw[idx];
    if (tid < 64) {
        sb[tid] = cb[tid];
        if (first) sst[tid] = g_stats[n * 64 + tid];
    }
    __syncthreads();
    float xv[64];
    const float* xb = (first ? g_bufB : g_bufA) + (size_t)n * 64 * HW + p;
    float* xout = g_bufA + (size_t)n * 64 * HW + p;
    #pragma unroll
    for (int i = 0; i < 64; i++) {
        float v = xb[(size_t)i * HW];
        if (first) {
            float2 st = sst[i];
            v = gelu_f((v - st.x) * st.y);
            xout[(size_t)i * HW] = v;
        }
        xv[i] = v;
    }
    float* ob = g_bufB + (size_t)n * 64 * HW + p;
    for (int o = 0; o < 64; o++) {
        float a = sb[o];
        const float4* w4 = (const float4*)(sw + o * 64);
        #pragma unroll
        for (int i4 = 0; i4 < 16; i4++) {
            float4 w = w4[i4];
            a = fmaf(w.x, xv[4 * i4],     a);
            a = fmaf(w.y, xv[4 * i4 + 1], a);
            a = fmaf(w.z, xv[4 * i4 + 2], a);
            a = fmaf(w.w, xv[4 * i4 + 3], a);
        }
        ob[(size_t)o * HW] = a;
    }
}

// forward W-DFT: Zw[row][k] = sum_w x[row][w] * e^{-2pi i k w / 256}
__global__ __launch_bounds__(256) void k_fwdW() {
    __shared__ float smx[32 * 256];
    int tid = threadIdx.x;
    int row0 = blockIdx.x * 32;
    for (int idx = tid; idx < 8192; idx += 256)
        smx[idx] = g_bufA[(size_t)row0 * 256 + idx];
    __syncthreads();
    int k = tid & 15, rg = tid >> 4;
    int r0 = rg * 2, r1 = r0 + 1;
    float a0r = 0, a0i = 0, a1r = 0, a1i = 0;
    const float2* twp = (const float2*)g_twfw;   // [w*16 + k]
    #pragma unroll 2
    for (int w = 0; w < 256; w += 4) {
        float4 x0 = *(const float4*)&smx[r0 * 256 + w];
        float4 x1 = *(const float4*)&smx[r1 * 256 + w];
        float2 t0 = twp[(w + 0) * 16 + k];
        float2 t1 = twp[(w + 1) * 16 + k];
        float2 t2 = twp[(w + 2) * 16 + k];
        float2 t3 = twp[(w + 3) * 16 + k];
        a0r = fmaf(x0.x, t0.x, a0r); a0i = fmaf(x0.x, t0.y, a0i);
        a0r = fmaf(x0.y, t1.x, a0r); a0i = fmaf(x0.y, t1.y, a0i);
        a0r = fmaf(x0.z, t2.x, a0r); a0i = fmaf(x0.z, t2.y, a0i);
        a0r = fmaf(x0.w, t3.x, a0r); a0i = fmaf(x0.w, t3.y, a0i);
        a1r = fmaf(x1.x, t0.x, a1r); a1i = fmaf(x1.x, t0.y, a1i);
        a1r = fmaf(x1.y, t1.x, a1r); a1i = fmaf(x1.y, t1.y, a1i);
        a1r = fmaf(x1.z, t2.x, a1r); a1i = fmaf(x1.z, t2.y, a1i);
        a1r = fmaf(x1.w, t3.x, a1r); a1i = fmaf(x1.w, t3.y, a1i);
    }
    g_fw[(size_t)(row0 + r0) * 16 + k] = make_float2(a0r, a0i);
    g_fw[(size_t)(row0 + r1) * 16 + k] = make_float2(a1r, a1i);
}

// forward H-DFT (rows 0..15 & 112..127), output pair (r, r+16) shares z loads
__global__ __launch_bounds__(256) void k_fwdH() {
    __shared__ float2 smz[2048];
    int tid = threadIdx.x;
    int b = blockIdx.x;          // n*64 + e
    int n = b >> 6, e = b & 63;
    for (int idx = tid; idx < 2048; idx += 256)
        smz[idx] = g_fw[(size_t)b * 2048 + idx];
    __syncthreads();
    int k = tid & 15, rr = tid >> 4;
    float ar0 = 0, ai0 = 0, ar1 = 0, ai1 = 0;
    #pragma unroll 4
    for (int h = 0; h < 128; h++) {
        float2 z = smz[h * 16 + k];
        float2 tA = g_twh[h * 32 + rr];
        float2 tB = g_twh[h * 32 + rr + 16];
        ar0 += z.x * tA.x + z.y * tA.y;
        ai0 += z.y * tA.x - z.x * tA.y;
        ar1 += z.x * tB.x + z.y * tB.y;
        ai1 += z.y * tB.x - z.x * tB.y;
    }
    g_cf[((size_t)n * 512 + rr * 16 + k) * 64 + e] =
        make_float2(ar0 * SCALE_O, ai0 * SCALE_O);
    g_cf[((size_t)n * 512 + (rr + 16) * 16 + k) * 64 + e] =
        make_float2(ar1 * SCALE_O, ai1 * SCALE_O);
}

// spectral multiply: one block per mode m, all 10 batch images per block
__global__ __launch_bounds__(128) void k_spec(int l) {
    __shared__ float2 sc[10][64];
    int tid = threadIdx.x;
    int m = blockIdx.x;            // 0..511
    for (int idx = tid; idx < 640; idx += 128) {
        int n = idx >> 6, i = idx & 63;
        sc[n][i] = g_cf[((size_t)n * 512 + m) * 64 + i];
    }
    __syncthreads();
    int o = tid & 63, nh = tid >> 6;
    int r = m >> 4, k = m & 15;
    int q = r >> 4;
    int m2 = (r & 15) * 16 + k;
    const float2* wp = g_wt + (size_t)((l * 2 + q) * 256 + m2) * 4096 + o;
    float ar[5] = {0, 0, 0, 0, 0}, ai[5] = {0, 0, 0, 0, 0};
    #pragma unroll 2
    for (int i = 0; i < 64; i++) {
        float2 w = wp[(size_t)i * 64];
        #pragma unroll
        for (int j = 0; j < 5; j++) {
            float2 c = sc[nh * 5 + j][i];
            ar[j] = fmaf(c.x, w.x, fmaf(-c.y, w.y, ar[j]));
            ai[j] = fmaf(c.x, w.y, fmaf(c.y, w.x, ai[j]));
        }
    }
    #pragma unroll
    for (int j = 0; j < 5; j++)
        g_cf2[((size_t)(nh * 5 + j) * 512 + m) * 64 + o] = make_float2(ar[j], ai[j]);
}

// FUSED inverse H + inverse W (C2R) + conv1x1-add + gelu.
__global__ __launch_bounds__(256) void k_invHW_gelu() {
    __shared__ float2 sz[512];
    __shared__ float  zz[32][32];
    int tid = threadIdx.x;
    int hq = blockIdx.x;
    int b  = blockIdx.y;             // n*64 + o
    int n = b >> 6, oo = b & 63;
    for (int m = tid; m < 512; m += 256)
        sz[m] = g_cf2[((size_t)n * 512 + m) * 64 + oo];
    __syncthreads();
    for (int oi = tid; oi < 512; oi += 256) {
        int hp = oi >> 4, k = oi & 15;
        int h = hq * 32 + hp;
        float ar = 0, ai = 0;
        #pragma unroll
        for (int r = 0; r < 32; r++) {
            float2 sp = sz[r * 16 + k];
            float2 t = g_twh[h * 32 + r];
            ar += sp.x * t.x - sp.y * t.y;
            ai += sp.x * t.y + sp.y * t.x;
        }
        zz[hp][2 * k]     = ar;
        zz[hp][2 * k + 1] = ai;
    }
    __syncthreads();
    int tx = tid & 63, ry = tid >> 6;
    int w0 = tx * 4;
    const float4* tp = (const float4*)g_tiw;
    size_t rowbase = (size_t)b * 128 + hq * 32;
    #pragma unroll
    for (int rg = 0; rg < 4; rg++) {
        int hA = rg * 8 + ry * 2, hB = hA + 1;
        float aA0 = 0, aA1 = 0, aA2 = 0, aA3 = 0;
        float aB0 = 0, aB1 = 0, aB2 = 0, aB3 = 0;
        #pragma unroll 4
        for (int j = 0; j < 32; j++) {
            float4 tv = tp[j * 64 + tx];
            float zA = zz[hA][j], zB = zz[hB][j];
            aA0 = fmaf(zA, tv.x, aA0); aA1 = fmaf(zA, tv.y, aA1);
            aA2 = fmaf(zA, tv.z, aA2); aA3 = fmaf(zA, tv.w, aA3);
            aB0 = fmaf(zB, tv.x, aB0); aB1 = fmaf(zB, tv.y, aB1);
            aB2 = fmaf(zB, tv.z, aB2); aB3 = fmaf(zB, tv.w, aB3);
        }
        size_t pA = (rowbase + hA) * Wd + w0;
        size_t pB = (rowbase + hB) * Wd + w0;
        float4 cA = *(const float4*)&g_bufB[pA];
        float4 cB = *(const float4*)&g_bufB[pB];
        float4 oA = make_float4(gelu_f(aA0 + cA.x), gelu_f(aA1 + cA.y),
                                gelu_f(aA2 + cA.z), gelu_f(aA3 + cA.w));
        float4 oB = make_float4(gelu_f(aB0 + cB.x), gelu_f(aB1 + cB.y),
                                gelu_f(aB2 + cB.z), gelu_f(aB3 + cB.w));
        *(float4*)&g_bufA[pA] = oA;
        *(float4*)&g_bufA[pB] = oB;
    }
}

__global__ __launch_bounds__(256) void k_downdim(const float* __restrict__ dw,
                                                 const float* __restrict__ db,
                                                 float* __restrict__ out) {
    __shared__ float sdw[128];
    __shared__ float sdb[2];
    int tid = threadIdx.x;
    if (tid < 128) sdw[tid] = dw[tid];
    if (tid < 2) sdb[tid] = db[tid];
    __syncthreads();
    int t = blockIdx.x * blockDim.x + tid;   // Nn*HW/4 threads
    if (t >= Nn * HW / 4) return;
    int n = t >> 13, p4 = (t & 8191) << 2;
    float4 c0 = make_float4(sdb[0], sdb[0], sdb[0], sdb[0]);
    float4 c1 = make_float4(sdb[1], sdb[1], sdb[1], sdb[1]);
    const float* xb = g_bufA + (size_t)n * 64 * HW + p4;
    #pragma unroll 4
    for (int e = 0; e < 64; e++) {
        float4 v = *(const float4*)&xb[(size_t)e * HW];
        float w0 = sdw[e], w1 = sdw[64 + e];
        c0.x = fmaf(w0, v.x, c0.x); c0.y = fmaf(w0, v.y, c0.y);
        c0.z = fmaf(w0, v.z, c0.z); c0.w = fmaf(w0, v.w, c0.w);
        c1.x = fmaf(w1, v.x, c1.x); c1.y = fmaf(w1, v.y, c1.y);
        c1.z = fmaf(w1, v.z, c1.z); c1.w = fmaf(w1, v.w, c1.w);
    }
    *(float4*)&out[(size_t)(n * 2) * HW + p4]     = c0;
    *(float4*)&out[(size_t)(n * 2 + 1) * HW + p4] = c1;
}

extern "C" void kernel_launch(void* const* d_in, const int* in_sizes, int n_in,
                              void* d_out, int out_size) {
    (void)in_sizes; (void)n_in; (void)out_size;
    const float* sensor    = (const float*)d_in[0];
    const float* updim_w   = (const float*)d_in[1];
    const float* updim_b   = (const float*)d_in[2];
    const float* smooth_w  = (const float*)d_in[3];
    // d_in[4] smooth_b: cancels exactly under InstanceNorm(affine=False)
    const float* fno_wr    = (const float*)d_in[5];
    const float* fno_wi    = (const float*)d_in[6];
    const float* fno_cw    = (const float*)d_in[7];
    const float* fno_cb    = (const float*)d_in[8];
    const float* downdim_w = (const float*)d_in[9];
    const float* downdim_b = (const float*)d_in[10];
    float* out = (float*)d_out;

    // k_conv_mma sits in the ncu-profiled launch slot (4th)
    k_prep_tw<<<32, 256>>>();
    k_prep_wc<<<64, 256>>>(smooth_w);
    k_updim<<<NEHW / 4 / 256, 256>>>(sensor, updim_w, updim_b);
    k_conv_mma<<<dim3(16, 32, 10), 256>>>();
    k_stats<<<640, 256>>>();
    k_prep_wt<<<32768, 256>>>(fno_wr, fno_wi);

    for (int l = 0; l < 4; l++) {
        k_conv1x1<<<dim3(128, 10), 256>>>(fno_cw + l * 4096, fno_cb + l * 64,
                                          l == 0 ? 1 : 0);
        k_fwdW<<<2560, 256>>>();
        k_fwdH<<<640, 256>>>();
        k_spec<<<512, 128>>>(l);
        k_invHW_gelu<<<dim3(4, 640), 256>>>();
    }

    k_downdim<<<(Nn * HW / 4 + 255) / 256, 256>>>(downdim_w, downdim_b, out);
}